// round 5
// baseline (speedup 1.0000x reference)
#include <cuda_runtime.h>
#include <math.h>

// Shapes (fixed by the problem)
#define HID      4096
#define NB       16      // batch
#define NH       32      // q heads
#define NKV      8       // kv heads
#define DHEAD    128
#define CTX_MAX  2048
#define BT_PER_SEQ 128
#define CHUNK    512     // GEMM K-chunk cached in smem (16*512*4 = 32KB)

// Scratch (no cudaMalloc allowed)
__device__ float g_qkv[NB * 6144];   // rows: [0,4096) q, [4096,5120) k, [5120,6144) v
__device__ float g_q  [NB * 4096];   // rope'd + pre-scaled q
__device__ float g_ctx[NB * 4096];   // attention output context

// ---------------------------------------------------------------------------
// GEMM: out[b, row] = dot(W[row, :], X[b, :])   (K = 4096, 16 batches)
// 32 rows per block, 256 threads. Thread (rp, lane) handles rows rp+{0,8,16,24},
// columns lane*4 within each 128-col sweep. Hidden chunk cached in smem,
// batch-major so a warp's LDS.128 covers 512 consecutive bytes (conflict-free).
// Three W pointers + boundaries let one launch fuse Wq/Wk/Wv.
// ---------------------------------------------------------------------------
__global__ __launch_bounds__(256, 2)
void gemm_b16(const float* __restrict__ W0, const float* __restrict__ W1,
              const float* __restrict__ W2, int bound0, int bound1,
              const float* __restrict__ X, float* __restrict__ out,
              int out_stride)
{
    __shared__ float hs[NB * CHUNK];
    const int t    = threadIdx.x;
    const int rp   = t >> 5;
    const int lane = t & 31;
    const int grow0 = blockIdx.x * 32;

    const float* W;
    int lrow0;
    if (grow0 < bound0)      { W = W0; lrow0 = grow0; }
    else if (grow0 < bound1) { W = W1; lrow0 = grow0 - bound0; }
    else                     { W = W2; lrow0 = grow0 - bound1; }

    float acc[4][16];
    #pragma unroll
    for (int j = 0; j < 4; j++)
        #pragma unroll
        for (int b = 0; b < 16; b++) acc[j][b] = 0.f;

    for (int kc = 0; kc < HID; kc += CHUNK) {
        // cooperative load of hidden chunk: 16 x 512 floats = 2048 float4
        #pragma unroll
        for (int i = 0; i < 8; i++) {
            int f4 = i * 256 + t;
            int b  = f4 >> 7;          // 128 float4 per batch row
            int c4 = f4 & 127;
            *(float4*)&hs[b * CHUNK + c4 * 4] =
                *(const float4*)&X[b * HID + kc + c4 * 4];
        }
        __syncthreads();

        const float* wbase = W + (size_t)(lrow0 + rp) * HID + kc;
        #pragma unroll 2
        for (int ci = 0; ci < 4; ci++) {
            int c = ci * 128 + lane * 4;
            float4 w0 = *(const float4*)(wbase + c);
            float4 w1 = *(const float4*)(wbase + 8  * HID + c);
            float4 w2 = *(const float4*)(wbase + 16 * HID + c);
            float4 w3 = *(const float4*)(wbase + 24 * HID + c);
            #pragma unroll
            for (int b = 0; b < 16; b++) {
                float4 h = *(const float4*)&hs[b * CHUNK + c];
                acc[0][b] += w0.x*h.x + w0.y*h.y + w0.z*h.z + w0.w*h.w;
                acc[1][b] += w1.x*h.x + w1.y*h.y + w1.z*h.z + w1.w*h.w;
                acc[2][b] += w2.x*h.x + w2.y*h.y + w2.z*h.z + w2.w*h.w;
                acc[3][b] += w3.x*h.x + w3.y*h.y + w3.z*h.z + w3.w*h.w;
            }
        }
        __syncthreads();
    }

    // warp-reduce 32 lane-partials per (row, batch), lane 0 writes
    #pragma unroll
    for (int j = 0; j < 4; j++) {
        #pragma unroll
        for (int b = 0; b < 16; b++) {
            float v = acc[j][b];
            v += __shfl_xor_sync(0xffffffffu, v, 16);
            v += __shfl_xor_sync(0xffffffffu, v, 8);
            v += __shfl_xor_sync(0xffffffffu, v, 4);
            v += __shfl_xor_sync(0xffffffffu, v, 2);
            v += __shfl_xor_sync(0xffffffffu, v, 1);
            if (lane == 0)
                out[b * out_stride + grow0 + rp + j * 8] = v;
        }
    }
}

// ---------------------------------------------------------------------------
// RoPE at single position pos = max(context_lens)-1 (reference semantics).
// Writes scaled q -> g_q, new_keys/new_values -> d_out slices.
// Double-precision trig: keeps |cos/sin - reference| ~1e-4 at arg ~2047.
// ---------------------------------------------------------------------------
__global__ void rope_kernel(const int* __restrict__ clens,
                            float* __restrict__ out_nk,
                            float* __restrict__ out_nv)
{
    const int b = blockIdx.x;
    const int t = threadIdx.x;

    int maxc = 1;
    #pragma unroll
    for (int i = 0; i < NB; i++) maxc = max(maxc, clens[i]);
    const double pos = (double)(maxc - 1);
    const float scale = 0.08838834764831845f;   // 1/sqrt(128)

    // 40 "heads" (32 q + 8 k) x 64 rotation pairs
    for (int idx = t; idx < 2560; idx += blockDim.x) {
        int head = idx >> 6;
        int d    = idx & 63;
        double x   = (double)(2 * d) / 128.0;
        double inv = exp(-x * log(10000.0));
        double e   = pos * inv;
        float c = (float)cos(e);
        float s = (float)sin(e);
        if (head < NH) {
            const float* src = &g_qkv[b * 6144 + head * DHEAD];
            float x1 = src[d], x2 = src[d + 64];
            g_q[b * 4096 + head * DHEAD + d]      = (x1 * c - x2 * s) * scale;
            g_q[b * 4096 + head * DHEAD + d + 64] = (x2 * c + x1 * s) * scale;
        } else {
            int kv = head - NH;
            const float* src = &g_qkv[b * 6144 + 4096 + kv * DHEAD];
            float x1 = src[d], x2 = src[d + 64];
            out_nk[b * 1024 + kv * DHEAD + d]      = x1 * c - x2 * s;
            out_nk[b * 1024 + kv * DHEAD + d + 64] = x2 * c + x1 * s;
        }
    }
    // new_values = v (no rope)
    for (int i = t; i < 1024; i += blockDim.x)
        out_nv[b * 1024 + i] = g_qkv[b * 6144 + 5120 + i];
}

// ---------------------------------------------------------------------------
// Paged GQA attention. Block = (kv head, batch). 8 warps; warp w owns
// positions w, w+8, ... Two passes over cached KV, scores in 32KB smem.
// 4 query heads share each K/V read (GQA G=4).
// ---------------------------------------------------------------------------
__global__ __launch_bounds__(256)
void attn_kernel(const float* __restrict__ kc, const float* __restrict__ vc,
                 const int* __restrict__ btab, const int* __restrict__ clens)
{
    __shared__ float sc[4 * CTX_MAX];   // scores, later reused for V partials
    __shared__ int   bts[BT_PER_SEQ];
    __shared__ float redbuf[4 * 8];
    __shared__ float mglob[4], dglob[4];

    const int kv = blockIdx.x;
    const int b  = blockIdx.y;
    const int t    = threadIdx.x;
    const int wid  = t >> 5;
    const int lane = t & 31;
    const int ctx  = clens[b];

    if (t < BT_PER_SEQ) bts[t] = btab[b * BT_PER_SEQ + t];
    __syncthreads();

    // q for the 4 heads of this kv group (already scaled by 1/sqrt(D))
    const float* qb = &g_q[b * 4096 + kv * 4 * DHEAD];
    float4 q0 = *(const float4*)&qb[0 * DHEAD + lane * 4];
    float4 q1 = *(const float4*)&qb[1 * DHEAD + lane * 4];
    float4 q2 = *(const float4*)&qb[2 * DHEAD + lane * 4];
    float4 q3 = *(const float4*)&qb[3 * DHEAD + lane * 4];

    // ---- pass 1: scores -------------------------------------------------
    #pragma unroll 2
    for (int p = wid; p < ctx; p += 8) {
        int blk = bts[p >> 4];
        const float* kp = kc + (((size_t)blk * 16 + (p & 15)) * NKV + kv) * DHEAD;
        float4 k4 = *(const float4*)(kp + lane * 4);
        float s0 = q0.x*k4.x + q0.y*k4.y + q0.z*k4.z + q0.w*k4.w;
        float s1 = q1.x*k4.x + q1.y*k4.y + q1.z*k4.z + q1.w*k4.w;
        float s2 = q2.x*k4.x + q2.y*k4.y + q2.z*k4.z + q2.w*k4.w;
        float s3 = q3.x*k4.x + q3.y*k4.y + q3.z*k4.z + q3.w*k4.w;
        // merged 4-value cross-warp reduction (9 shuffles)
        s0 += __shfl_xor_sync(0xffffffffu, s0, 16);
        s1 += __shfl_xor_sync(0xffffffffu, s1, 16);
        s2 += __shfl_xor_sync(0xffffffffu, s2, 16);
        s3 += __shfl_xor_sync(0xffffffffu, s3, 16);
        float x = (lane & 16) ? s1 : s0;
        float y = (lane & 16) ? s3 : s2;
        x += __shfl_xor_sync(0xffffffffu, x, 8);
        y += __shfl_xor_sync(0xffffffffu, y, 8);
        float z = (lane & 8) ? y : x;
        z += __shfl_xor_sync(0xffffffffu, z, 4);
        z += __shfl_xor_sync(0xffffffffu, z, 2);
        z += __shfl_xor_sync(0xffffffffu, z, 1);
        if ((lane & 7) == 0) {
            int h = ((lane >> 4) & 1) | ((lane >> 2) & 2); // 0->h0 16->h1 8->h2 24->h3
            sc[h * CTX_MAX + p] = z;
        }
    }
    __syncthreads();

    // ---- softmax: max ----------------------------------------------------
    float m0 = -1e30f, m1 = -1e30f, m2 = -1e30f, m3 = -1e30f;
    for (int p = t; p < ctx; p += 256) {
        m0 = fmaxf(m0, sc[0 * CTX_MAX + p]);
        m1 = fmaxf(m1, sc[1 * CTX_MAX + p]);
        m2 = fmaxf(m2, sc[2 * CTX_MAX + p]);
        m3 = fmaxf(m3, sc[3 * CTX_MAX + p]);
    }
    #pragma unroll
    for (int o = 16; o; o >>= 1) {
        m0 = fmaxf(m0, __shfl_xor_sync(0xffffffffu, m0, o));
        m1 = fmaxf(m1, __shfl_xor_sync(0xffffffffu, m1, o));
        m2 = fmaxf(m2, __shfl_xor_sync(0xffffffffu, m2, o));
        m3 = fmaxf(m3, __shfl_xor_sync(0xffffffffu, m3, o));
    }
    if (lane == 0) {
        redbuf[0 * 8 + wid] = m0; redbuf[1 * 8 + wid] = m1;
        redbuf[2 * 8 + wid] = m2; redbuf[3 * 8 + wid] = m3;
    }
    __syncthreads();
    if (t < 4) {
        float mm = -1e30f;
        #pragma unroll
        for (int w = 0; w < 8; w++) mm = fmaxf(mm, redbuf[t * 8 + w]);
        mglob[t] = mm;
    }
    __syncthreads();

    // ---- softmax: exp + sum ----------------------------------------------
    const float M0 = mglob[0], M1 = mglob[1], M2 = mglob[2], M3 = mglob[3];
    float d0 = 0.f, d1 = 0.f, d2 = 0.f, d3 = 0.f;
    for (int p = t; p < ctx; p += 256) {
        float e0 = __expf(sc[0 * CTX_MAX + p] - M0); sc[0 * CTX_MAX + p] = e0; d0 += e0;
        float e1 = __expf(sc[1 * CTX_MAX + p] - M1); sc[1 * CTX_MAX + p] = e1; d1 += e1;
        float e2 = __expf(sc[2 * CTX_MAX + p] - M2); sc[2 * CTX_MAX + p] = e2; d2 += e2;
        float e3 = __expf(sc[3 * CTX_MAX + p] - M3); sc[3 * CTX_MAX + p] = e3; d3 += e3;
    }
    #pragma unroll
    for (int o = 16; o; o >>= 1) {
        d0 += __shfl_xor_sync(0xffffffffu, d0, o);
        d1 += __shfl_xor_sync(0xffffffffu, d1, o);
        d2 += __shfl_xor_sync(0xffffffffu, d2, o);
        d3 += __shfl_xor_sync(0xffffffffu, d3, o);
    }
    __syncthreads();   // all sc writes done; safe to reuse redbuf
    if (lane == 0) {
        redbuf[0 * 8 + wid] = d0; redbuf[1 * 8 + wid] = d1;
        redbuf[2 * 8 + wid] = d2; redbuf[3 * 8 + wid] = d3;
    }
    __syncthreads();
    if (t < 4) {
        float ss = 0.f;
        #pragma unroll
        for (int w = 0; w < 8; w++) ss += redbuf[t * 8 + w];
        dglob[t] = 1.f / ss;
    }

    // ---- pass 2: probs @ V -------------------------------------------------
    float4 a0 = {0,0,0,0}, a1 = {0,0,0,0}, a2 = {0,0,0,0}, a3 = {0,0,0,0};
    #pragma unroll 2
    for (int p = wid; p < ctx; p += 8) {
        int blk = bts[p >> 4];
        const float* vp = vc + (((size_t)blk * 16 + (p & 15)) * NKV + kv) * DHEAD;
        float4 v4 = *(const float4*)(vp + lane * 4);
        float p0 = sc[0 * CTX_MAX + p], p1 = sc[1 * CTX_MAX + p];
        float p2 = sc[2 * CTX_MAX + p], p3 = sc[3 * CTX_MAX + p];
        a0.x += p0*v4.x; a0.y += p0*v4.y; a0.z += p0*v4.z; a0.w += p0*v4.w;
        a1.x += p1*v4.x; a1.y += p1*v4.y; a1.z += p1*v4.z; a1.w += p1*v4.w;
        a2.x += p2*v4.x; a2.y += p2*v4.y; a2.z += p2*v4.z; a2.w += p2*v4.w;
        a3.x += p3*v4.x; a3.y += p3*v4.y; a3.z += p3*v4.z; a3.w += p3*v4.w;
    }
    __syncthreads();   // probs fully consumed; reuse sc as partial buffer

    float* part = sc;  // 8 warps * 512 floats = 16KB (fits in sc)
    *(float4*)&part[wid * 512 + 0 * DHEAD + lane * 4] = a0;
    *(float4*)&part[wid * 512 + 1 * DHEAD + lane * 4] = a1;
    *(float4*)&part[wid * 512 + 2 * DHEAD + lane * 4] = a2;
    *(float4*)&part[wid * 512 + 3 * DHEAD + lane * 4] = a3;
    __syncthreads();

    for (int o = t; o < 512; o += 256) {
        int h = o >> 7;
        float s = 0.f;
        #pragma unroll
        for (int w = 0; w < 8; w++) s += part[w * 512 + o];
        g_ctx[b * 4096 + kv * 512 + o] = s * dglob[h];
    }
}

// ---------------------------------------------------------------------------
extern "C" void kernel_launch(void* const* d_in, const int* in_sizes, int n_in,
                              void* d_out, int out_size)
{
    const float* hidden = (const float*)d_in[0];
    const float* kcache = (const float*)d_in[1];
    const float* vcache = (const float*)d_in[2];
    const int*   btab   = (const int*)  d_in[3];
    const int*   clens  = (const int*)  d_in[4];
    // weights are always the last 4 inputs (block_size scalar may or may not
    // be materialized as an input)
    const int base = n_in - 4;
    const float* Wq = (const float*)d_in[base + 0];
    const float* Wk = (const float*)d_in[base + 1];
    const float* Wv = (const float*)d_in[base + 2];
    const float* Wo = (const float*)d_in[base + 3];
    float* out = (float*)d_out;

    float *qkv_p, *ctx_p;
    cudaGetSymbolAddress((void**)&qkv_p, g_qkv);
    cudaGetSymbolAddress((void**)&ctx_p, g_ctx);

    // 1) fused Q/K/V projection: rows [0,4096)=Wq, [4096,5120)=Wk, [5120,6144)=Wv
    gemm_b16<<<192, 256>>>(Wq, Wk, Wv, 4096, 5120, hidden, qkv_p, 6144);

    // 2) RoPE + emit new_keys / new_values
    rope_kernel<<<16, 256>>>(clens, out + 65536, out + 81920);

    // 3) paged GQA attention -> g_ctx
    attn_kernel<<<dim3(NKV, NB), 256>>>(kcache, vcache, btab, clens);

    // 4) output projection -> attn_out
    gemm_b16<<<128, 256>>>(Wo, Wo, Wo, 1 << 30, 1 << 30, ctx_p, out, 4096);
}

// round 6
// speedup vs baseline: 2.4195x; 2.4195x over previous
#include <cuda_runtime.h>
#include <math.h>

// Shapes (fixed by the problem)
#define HID      4096
#define NB       16      // batch
#define NH       32      // q heads
#define NKV      8       // kv heads
#define DHEAD    128
#define CTX_MAX  2048
#define BT_PER_SEQ 128
#define CHUNK    512     // GEMM K-chunk cached in smem (16*512*4 = 32KB)

// Scratch (no cudaMalloc allowed)
__device__ float g_qkv[NB * 6144];   // rows: [0,4096) q, [4096,5120) k, [5120,6144) v
__device__ float g_q  [NB * 4096];   // rope'd + pre-scaled q
__device__ float g_ctx[NB * 4096];   // attention output context

// packed fp32x2 FMA (FFMA2) — 2x fp32 FMA throughput vs scalar FFMA on sm_103a
__device__ __forceinline__ void fma2(unsigned long long& acc,
                                     unsigned long long a,
                                     unsigned long long b) {
    asm("fma.rn.f32x2 %0, %1, %2, %0;" : "+l"(acc) : "l"(a), "l"(b));
}
__device__ __forceinline__ float unpack_sum(unsigned long long v) {
    float lo, hi;
    asm("mov.b64 {%0, %1}, %2;" : "=f"(lo), "=f"(hi) : "l"(v));
    return lo + hi;
}

// ---------------------------------------------------------------------------
// GEMM: out[b, row] = dot(W[row, :], X[b, :])   (K = 4096, 16 batches)
// 16 rows per block, 256 threads. Warps split into two batch halves (8 each);
// warp group wg owns rows wg*4..wg*4+3, lane covers cols lane*4 per 128-sweep.
// Accumulation in packed f32x2 (even/odd column partials), combined at epilogue.
// Per ci: 4 LDG.128 + 8 LDS.128 + 64 FFMA2 per thread.
// ---------------------------------------------------------------------------
__global__ __launch_bounds__(256, 2)
void gemm_b16(const float* __restrict__ W0, const float* __restrict__ W1,
              const float* __restrict__ W2, int bound0, int bound1,
              const float* __restrict__ X, float* __restrict__ out,
              int out_stride)
{
    __shared__ float hs[NB * CHUNK];
    const int t    = threadIdx.x;
    const int lane = t & 31;
    const int wg   = (t >> 5) & 3;   // row group: rows wg*4 .. wg*4+3
    const int bh   = t >> 7;         // batch half: batches bh*8 .. bh*8+7
    const int grow0 = blockIdx.x * 16;

    const float* W;
    int lrow0;
    if (grow0 < bound0)      { W = W0; lrow0 = grow0; }
    else if (grow0 < bound1) { W = W1; lrow0 = grow0 - bound0; }
    else                     { W = W2; lrow0 = grow0 - bound1; }

    unsigned long long acc[4][8];
    #pragma unroll
    for (int r = 0; r < 4; r++)
        #pragma unroll
        for (int b = 0; b < 8; b++) acc[r][b] = 0ull;

    const float* wrow = W + (size_t)(lrow0 + wg * 4) * HID;

    for (int kc = 0; kc < HID; kc += CHUNK) {
        // cooperative load of hidden chunk: 16 x 512 floats = 2048 float4
        #pragma unroll
        for (int i = 0; i < 8; i++) {
            int f4 = i * 256 + t;
            int b  = f4 >> 7;
            int c4 = f4 & 127;
            *(float4*)&hs[b * CHUNK + c4 * 4] =
                *(const float4*)&X[b * HID + kc + c4 * 4];
        }
        __syncthreads();

        const float* wb = wrow + kc;
        #pragma unroll
        for (int ci = 0; ci < 4; ci++) {
            int c = ci * 128 + lane * 4;
            ulonglong2 w0 = *(const ulonglong2*)(wb + c);
            ulonglong2 w1 = *(const ulonglong2*)(wb + HID + c);
            ulonglong2 w2 = *(const ulonglong2*)(wb + 2 * HID + c);
            ulonglong2 w3 = *(const ulonglong2*)(wb + 3 * HID + c);
            #pragma unroll
            for (int b = 0; b < 8; b++) {
                ulonglong2 h = *(const ulonglong2*)&hs[(bh * 8 + b) * CHUNK + c];
                fma2(acc[0][b], w0.x, h.x); fma2(acc[0][b], w0.y, h.y);
                fma2(acc[1][b], w1.x, h.x); fma2(acc[1][b], w1.y, h.y);
                fma2(acc[2][b], w2.x, h.x); fma2(acc[2][b], w2.y, h.y);
                fma2(acc[3][b], w3.x, h.x); fma2(acc[3][b], w3.y, h.y);
            }
        }
        __syncthreads();
    }

    // combine even/odd partials, warp-reduce lane partials, lane 0 writes
    #pragma unroll
    for (int r = 0; r < 4; r++) {
        #pragma unroll
        for (int b = 0; b < 8; b++) {
            float v = unpack_sum(acc[r][b]);
            v += __shfl_xor_sync(0xffffffffu, v, 16);
            v += __shfl_xor_sync(0xffffffffu, v, 8);
            v += __shfl_xor_sync(0xffffffffu, v, 4);
            v += __shfl_xor_sync(0xffffffffu, v, 2);
            v += __shfl_xor_sync(0xffffffffu, v, 1);
            if (lane == 0)
                out[(bh * 8 + b) * out_stride + grow0 + wg * 4 + r] = v;
        }
    }
}

// ---------------------------------------------------------------------------
// RoPE at single position pos = max(context_lens)-1 (reference semantics).
// Trig computed ONCE per block (64 threads, fp64) into smem — the previous
// version spent ~10us in per-element fp64 transcendentals.
// ---------------------------------------------------------------------------
__global__ void rope_kernel(const int* __restrict__ clens,
                            float* __restrict__ out_nk,
                            float* __restrict__ out_nv)
{
    __shared__ float cs[64], sn[64];
    const int b = blockIdx.x;
    const int t = threadIdx.x;

    if (t < 64) {
        int maxc = 1;
        #pragma unroll
        for (int i = 0; i < NB; i++) maxc = max(maxc, clens[i]);
        double pos = (double)(maxc - 1);
        double x   = (double)(2 * t) / 128.0;
        double inv = exp(-x * log(10000.0));
        double e   = pos * inv;
        cs[t] = (float)cos(e);
        sn[t] = (float)sin(e);
    }
    __syncthreads();

    const float scale = 0.08838834764831845f;   // 1/sqrt(128)

    // 40 "heads" (32 q + 8 k) x 64 rotation pairs
    for (int idx = t; idx < 2560; idx += blockDim.x) {
        int head = idx >> 6;
        int d    = idx & 63;
        float c = cs[d], s = sn[d];
        if (head < NH) {
            const float* src = &g_qkv[b * 6144 + head * DHEAD];
            float x1 = src[d], x2 = src[d + 64];
            g_q[b * 4096 + head * DHEAD + d]      = (x1 * c - x2 * s) * scale;
            g_q[b * 4096 + head * DHEAD + d + 64] = (x2 * c + x1 * s) * scale;
        } else {
            int kv = head - NH;
            const float* src = &g_qkv[b * 6144 + 4096 + kv * DHEAD];
            float x1 = src[d], x2 = src[d + 64];
            out_nk[b * 1024 + kv * DHEAD + d]      = x1 * c - x2 * s;
            out_nk[b * 1024 + kv * DHEAD + d + 64] = x2 * c + x1 * s;
        }
    }
    // new_values = v (no rope)
    for (int i = t; i < 1024; i += blockDim.x)
        out_nv[b * 1024 + i] = g_qkv[b * 6144 + 5120 + i];
}

// ---------------------------------------------------------------------------
// Paged GQA attention. Block = (kv head, batch). 16 warps; each warp batches
// 8 positions of K/V loads before computing (8 in-flight LDG.128 per warp ->
// ~128 outstanding loads/SM, vs 8 before). Scores in 32KB smem, two passes.
// ---------------------------------------------------------------------------
__global__ __launch_bounds__(512)
void attn_kernel(const float* __restrict__ kc, const float* __restrict__ vc,
                 const int* __restrict__ btab, const int* __restrict__ clens)
{
    __shared__ float sc[4 * CTX_MAX];   // scores; later reused for V partials
    __shared__ int   bts[BT_PER_SEQ];
    __shared__ float redbuf[4 * 16];
    __shared__ float mglob[4], dglob[4];

    const int kv = blockIdx.x;
    const int b  = blockIdx.y;
    const int t    = threadIdx.x;
    const int wid  = t >> 5;            // 0..15
    const int lane = t & 31;
    const int ctx  = clens[b];

    if (t < BT_PER_SEQ) bts[t] = btab[b * BT_PER_SEQ + t];
    __syncthreads();

    // q for the 4 heads of this kv group (already scaled by 1/sqrt(D))
    const float* qb = &g_q[b * 4096 + kv * 4 * DHEAD];
    float4 q0 = *(const float4*)&qb[0 * DHEAD + lane * 4];
    float4 q1 = *(const float4*)&qb[1 * DHEAD + lane * 4];
    float4 q2 = *(const float4*)&qb[2 * DHEAD + lane * 4];
    float4 q3 = *(const float4*)&qb[3 * DHEAD + lane * 4];

    // ---- pass 1: scores (8 positions in flight per warp) -----------------
    for (int base = wid * 8; base < ctx; base += 128) {
        float4 k[8];
        #pragma unroll
        for (int i = 0; i < 8; i++) {
            int p = base + i;
            if (p < ctx) {
                int blk = bts[p >> 4];
                k[i] = *(const float4*)(kc +
                        (((size_t)blk * 16 + (p & 15)) * NKV + kv) * DHEAD + lane * 4);
            } else {
                k[i] = make_float4(0.f, 0.f, 0.f, 0.f);
            }
        }
        #pragma unroll
        for (int i = 0; i < 8; i++) {
            int p = base + i;
            if (p < ctx) {
                float s0 = q0.x*k[i].x + q0.y*k[i].y + q0.z*k[i].z + q0.w*k[i].w;
                float s1 = q1.x*k[i].x + q1.y*k[i].y + q1.z*k[i].z + q1.w*k[i].w;
                float s2 = q2.x*k[i].x + q2.y*k[i].y + q2.z*k[i].z + q2.w*k[i].w;
                float s3 = q3.x*k[i].x + q3.y*k[i].y + q3.z*k[i].z + q3.w*k[i].w;
                // merged 4-value cross-warp reduction (9 shuffles)
                s0 += __shfl_xor_sync(0xffffffffu, s0, 16);
                s1 += __shfl_xor_sync(0xffffffffu, s1, 16);
                s2 += __shfl_xor_sync(0xffffffffu, s2, 16);
                s3 += __shfl_xor_sync(0xffffffffu, s3, 16);
                float x = (lane & 16) ? s1 : s0;
                float y = (lane & 16) ? s3 : s2;
                x += __shfl_xor_sync(0xffffffffu, x, 8);
                y += __shfl_xor_sync(0xffffffffu, y, 8);
                float z = (lane & 8) ? y : x;
                z += __shfl_xor_sync(0xffffffffu, z, 4);
                z += __shfl_xor_sync(0xffffffffu, z, 2);
                z += __shfl_xor_sync(0xffffffffu, z, 1);
                if ((lane & 7) == 0) {
                    int h = ((lane >> 4) & 1) | ((lane >> 2) & 2);
                    sc[h * CTX_MAX + p] = z;
                }
            }
        }
    }
    __syncthreads();

    // ---- softmax: max ----------------------------------------------------
    float m0 = -1e30f, m1 = -1e30f, m2 = -1e30f, m3 = -1e30f;
    for (int p = t; p < ctx; p += 512) {
        m0 = fmaxf(m0, sc[0 * CTX_MAX + p]);
        m1 = fmaxf(m1, sc[1 * CTX_MAX + p]);
        m2 = fmaxf(m2, sc[2 * CTX_MAX + p]);
        m3 = fmaxf(m3, sc[3 * CTX_MAX + p]);
    }
    #pragma unroll
    for (int o = 16; o; o >>= 1) {
        m0 = fmaxf(m0, __shfl_xor_sync(0xffffffffu, m0, o));
        m1 = fmaxf(m1, __shfl_xor_sync(0xffffffffu, m1, o));
        m2 = fmaxf(m2, __shfl_xor_sync(0xffffffffu, m2, o));
        m3 = fmaxf(m3, __shfl_xor_sync(0xffffffffu, m3, o));
    }
    if (lane == 0) {
        redbuf[0 * 16 + wid] = m0; redbuf[1 * 16 + wid] = m1;
        redbuf[2 * 16 + wid] = m2; redbuf[3 * 16 + wid] = m3;
    }
    __syncthreads();
    if (t < 4) {
        float mm = -1e30f;
        #pragma unroll
        for (int w = 0; w < 16; w++) mm = fmaxf(mm, redbuf[t * 16 + w]);
        mglob[t] = mm;
    }
    __syncthreads();

    // ---- softmax: exp + sum ----------------------------------------------
    const float M0 = mglob[0], M1 = mglob[1], M2 = mglob[2], M3 = mglob[3];
    float d0 = 0.f, d1 = 0.f, d2 = 0.f, d3 = 0.f;
    for (int p = t; p < ctx; p += 512) {
        float e0 = __expf(sc[0 * CTX_MAX + p] - M0); sc[0 * CTX_MAX + p] = e0; d0 += e0;
        float e1 = __expf(sc[1 * CTX_MAX + p] - M1); sc[1 * CTX_MAX + p] = e1; d1 += e1;
        float e2 = __expf(sc[2 * CTX_MAX + p] - M2); sc[2 * CTX_MAX + p] = e2; d2 += e2;
        float e3 = __expf(sc[3 * CTX_MAX + p] - M3); sc[3 * CTX_MAX + p] = e3; d3 += e3;
    }
    #pragma unroll
    for (int o = 16; o; o >>= 1) {
        d0 += __shfl_xor_sync(0xffffffffu, d0, o);
        d1 += __shfl_xor_sync(0xffffffffu, d1, o);
        d2 += __shfl_xor_sync(0xffffffffu, d2, o);
        d3 += __shfl_xor_sync(0xffffffffu, d3, o);
    }
    __syncthreads();   // all sc writes done; safe to reuse redbuf
    if (lane == 0) {
        redbuf[0 * 16 + wid] = d0; redbuf[1 * 16 + wid] = d1;
        redbuf[2 * 16 + wid] = d2; redbuf[3 * 16 + wid] = d3;
    }
    __syncthreads();
    if (t < 4) {
        float ss = 0.f;
        #pragma unroll
        for (int w = 0; w < 16; w++) ss += redbuf[t * 16 + w];
        dglob[t] = 1.f / ss;
    }

    // ---- pass 2: probs @ V (8 positions in flight per warp) --------------
    float4 a0 = {0,0,0,0}, a1 = {0,0,0,0}, a2 = {0,0,0,0}, a3 = {0,0,0,0};
    for (int base = wid * 8; base < ctx; base += 128) {
        float4 v[8];
        #pragma unroll
        for (int i = 0; i < 8; i++) {
            int p = base + i;
            if (p < ctx) {
                int blk = bts[p >> 4];
                v[i] = *(const float4*)(vc +
                        (((size_t)blk * 16 + (p & 15)) * NKV + kv) * DHEAD + lane * 4);
            } else {
                v[i] = make_float4(0.f, 0.f, 0.f, 0.f);
            }
        }
        #pragma unroll
        for (int i = 0; i < 8; i++) {
            int p = base + i;
            if (p < ctx) {
                float p0 = sc[0 * CTX_MAX + p], p1 = sc[1 * CTX_MAX + p];
                float p2 = sc[2 * CTX_MAX + p], p3 = sc[3 * CTX_MAX + p];
                a0.x += p0*v[i].x; a0.y += p0*v[i].y; a0.z += p0*v[i].z; a0.w += p0*v[i].w;
                a1.x += p1*v[i].x; a1.y += p1*v[i].y; a1.z += p1*v[i].z; a1.w += p1*v[i].w;
                a2.x += p2*v[i].x; a2.y += p2*v[i].y; a2.z += p2*v[i].z; a2.w += p2*v[i].w;
                a3.x += p3*v[i].x; a3.y += p3*v[i].y; a3.z += p3*v[i].z; a3.w += p3*v[i].w;
            }
        }
    }
    __syncthreads();   // probs fully consumed; reuse sc as partial buffer

    float* part = sc;  // 16 warps * 512 floats = 32KB (== sc size)
    *(float4*)&part[wid * 512 + 0 * DHEAD + lane * 4] = a0;
    *(float4*)&part[wid * 512 + 1 * DHEAD + lane * 4] = a1;
    *(float4*)&part[wid * 512 + 2 * DHEAD + lane * 4] = a2;
    *(float4*)&part[wid * 512 + 3 * DHEAD + lane * 4] = a3;
    __syncthreads();

    {
        int o = t;                      // 512 threads, 512 outputs
        int h = o >> 7;
        float s = 0.f;
        #pragma unroll
        for (int w = 0; w < 16; w++) s += part[w * 512 + o];
        g_ctx[b * 4096 + kv * 512 + o] = s * dglob[h];
    }
}

// ---------------------------------------------------------------------------
extern "C" void kernel_launch(void* const* d_in, const int* in_sizes, int n_in,
                              void* d_out, int out_size)
{
    const float* hidden = (const float*)d_in[0];
    const float* kcache = (const float*)d_in[1];
    const float* vcache = (const float*)d_in[2];
    const int*   btab   = (const int*)  d_in[3];
    const int*   clens  = (const int*)  d_in[4];
    const int base = n_in - 4;
    const float* Wq = (const float*)d_in[base + 0];
    const float* Wk = (const float*)d_in[base + 1];
    const float* Wv = (const float*)d_in[base + 2];
    const float* Wo = (const float*)d_in[base + 3];
    float* out = (float*)d_out;

    float *qkv_p, *ctx_p;
    cudaGetSymbolAddress((void**)&qkv_p, g_qkv);
    cudaGetSymbolAddress((void**)&ctx_p, g_ctx);

    // 1) fused Q/K/V projection: rows [0,4096)=Wq, [4096,5120)=Wk, [5120,6144)=Wv
    gemm_b16<<<384, 256>>>(Wq, Wk, Wv, 4096, 5120, hidden, qkv_p, 6144);

    // 2) RoPE + emit new_keys / new_values
    rope_kernel<<<16, 256>>>(clens, out + 65536, out + 81920);

    // 3) paged GQA attention -> g_ctx
    attn_kernel<<<dim3(NKV, NB), 512>>>(kcache, vcache, btab, clens);

    // 4) output projection -> attn_out
    gemm_b16<<<256, 256>>>(Wo, Wo, Wo, 1 << 30, 1 << 30, ctx_p, out, 4096);
}